// round 1
// baseline (speedup 1.0000x reference)
#include <cuda_runtime.h>
#include <math.h>
#include <stddef.h>

#define B_   32
#define S_   512
#define E_   512
#define INNER_ 1024
#define NH_  4
#define DH_  256
#define M_TOK (B_*S_)   // 16384

// ---------------- scratch (device globals: allocation-free) ----------------
__device__ float g_h[(size_t)M_TOK*E_];          // LN'd embeddings      (32 MB)
__device__ float g_xm[(size_t)M_TOK*INNER_];     // up-proj first half   (64 MB)
__device__ float g_q[(size_t)B_*NH_*S_*DH_];     // q  [b][h][t][d]      (64 MB)
__device__ float g_k[(size_t)B_*NH_*S_*DH_];     // k                    (64 MB)
__device__ float g_v[(size_t)B_*NH_*S_*DH_];     // v                    (64 MB)
__device__ float g_ig[B_*NH_*S_];
__device__ float g_lf[B_*NH_*S_];                // log_sigmoid(fg)
__device__ float g_res_last[B_*E_];
__device__ float g_xa_last[B_*INNER_];
__device__ float g_hs[B_*INNER_];

// ---------------- K1: embedding gather + LayerNorm ----------------
__global__ void k1_embed_ln(const int* __restrict__ tokens,
                            const float* __restrict__ emb,
                            const float* __restrict__ ln1w)
{
    int m = blockIdx.x;
    int tid = threadIdx.x;           // 256 threads, 2 elems each
    int tok = tokens[m];
    float x0 = 0.f, x1 = 0.f;
    if (tok != 0) {                  // emb.at[0].set(0)
        const float* row = emb + (size_t)tok * E_;
        x0 = row[tid];
        x1 = row[tid + 256];
    }
    __shared__ float red[256];
    red[tid] = x0 + x1;
    __syncthreads();
    for (int o = 128; o > 0; o >>= 1) { if (tid < o) red[tid] += red[tid+o]; __syncthreads(); }
    float mean = red[0] * (1.f / E_);
    __syncthreads();
    red[tid] = x0*x0 + x1*x1;
    __syncthreads();
    for (int o = 128; o > 0; o >>= 1) { if (tid < o) red[tid] += red[tid+o]; __syncthreads(); }
    float var = red[0] * (1.f / E_) - mean*mean;
    float rstd = rsqrtf(var + 1e-5f);

    g_h[(size_t)m*E_ + tid]       = (x0 - mean) * rstd * ln1w[tid];
    g_h[(size_t)m*E_ + tid + 256] = (x1 - mean) * rstd * ln1w[tid + 256];

    if ((m & (S_-1)) == S_-1) {
        int b = m >> 9;
        g_res_last[b*E_ + tid]       = x0;
        g_res_last[b*E_ + tid + 256] = x1;
    }
}

// ---------------- K2: up-projection GEMM (first INNER cols only) ----------------
// C[m,n] = sum_k g_h[m,k] * wup[n,k],  M=16384, N=1024, K=512
#define BM 64
#define BN 64
#define BKK 32
__global__ void k2_gemm_up(const float* __restrict__ wup)
{
    __shared__ float As[BM][36];     // [m][k], padded, 16B-aligned rows
    __shared__ float Bs[BKK][68];    // [k][n], padded, 16B-aligned rows
    int tid = threadIdx.x;           // 256
    int tx = tid & 15, ty = tid >> 4;
    int m0 = blockIdx.y * BM;
    int n0 = blockIdx.x * BN;

    float4 acc[4];
    #pragma unroll
    for (int r = 0; r < 4; r++) acc[r] = make_float4(0.f, 0.f, 0.f, 0.f);

    for (int k0 = 0; k0 < E_; k0 += BKK) {
        #pragma unroll
        for (int j = 0; j < 2; j++) {
            int u = tid + j*256;
            int row = u >> 3, kq = u & 7;
            float4 av = *(const float4*)&g_h[(size_t)(m0+row)*E_ + k0 + kq*4];
            *(float4*)&As[row][kq*4] = av;
        }
        #pragma unroll
        for (int j = 0; j < 2; j++) {
            int u = tid + j*256;
            int n = u >> 3, kq = u & 7;
            float4 bv = *(const float4*)&wup[(size_t)(n0+n)*E_ + k0 + kq*4];
            Bs[kq*4+0][n] = bv.x; Bs[kq*4+1][n] = bv.y;
            Bs[kq*4+2][n] = bv.z; Bs[kq*4+3][n] = bv.w;
        }
        __syncthreads();
        #pragma unroll
        for (int kk = 0; kk < BKK; kk++) {
            float4 bv = *(const float4*)&Bs[kk][tx*4];
            float a0 = As[ty*4+0][kk];
            float a1 = As[ty*4+1][kk];
            float a2 = As[ty*4+2][kk];
            float a3 = As[ty*4+3][kk];
            acc[0].x += a0*bv.x; acc[0].y += a0*bv.y; acc[0].z += a0*bv.z; acc[0].w += a0*bv.w;
            acc[1].x += a1*bv.x; acc[1].y += a1*bv.y; acc[1].z += a1*bv.z; acc[1].w += a1*bv.w;
            acc[2].x += a2*bv.x; acc[2].y += a2*bv.y; acc[2].z += a2*bv.z; acc[2].w += a2*bv.w;
            acc[3].x += a3*bv.x; acc[3].y += a3*bv.y; acc[3].z += a3*bv.z; acc[3].w += a3*bv.w;
        }
        __syncthreads();
    }
    #pragma unroll
    for (int r = 0; r < 4; r++)
        *(float4*)&g_xm[(size_t)(m0 + ty*4 + r)*INNER_ + n0 + tx*4] = acc[r];
}

// ---------------- K3: causal conv + silu + block-diag q/k/v ----------------
// block = (b, 8 consecutive s); thread n (0..255) owns channels 4n..4n+3
__device__ __forceinline__ float silu_f(float x) { return x / (1.f + expf(-x)); }

__global__ void k3_conv_qkv(const float* __restrict__ convw, const float* __restrict__ convb,
                            const float* __restrict__ qw, const float* __restrict__ kw,
                            const float* __restrict__ vw)
{
    int n  = threadIdx.x;
    int b  = blockIdx.y;
    int s0 = blockIdx.x * 8;

    float cw[4][4], cb[4], qwr[4][4], kwr[4][4], vwr[4][4];
    #pragma unroll
    for (int o = 0; o < 4; o++) {
        cb[o] = convb[4*n + o];
        #pragma unroll
        for (int j = 0; j < 4; j++) cw[o][j] = convw[(4*n+o)*4 + j];
        #pragma unroll
        for (int i = 0; i < 4; i++) {
            qwr[o][i] = qw[(n*4+o)*4 + i];
            kwr[o][i] = kw[(n*4+o)*4 + i];
            vwr[o][i] = vw[(n*4+o)*4 + i];
        }
    }

    float win[4][4];                 // win[j] = x_m at s-3+j
    #pragma unroll
    for (int j = 0; j < 3; j++) {
        int s = s0 - 3 + j;
        if (s >= 0) {
            float4 t = *(const float4*)&g_xm[((size_t)b*S_ + s)*INNER_ + 4*n];
            win[j][0]=t.x; win[j][1]=t.y; win[j][2]=t.z; win[j][3]=t.w;
        } else {
            win[j][0]=win[j][1]=win[j][2]=win[j][3]=0.f;
        }
    }
    int h = n >> 6;
    int dbase = (n & 63) * 4;

    for (int ss = 0; ss < 8; ss++) {
        int s = s0 + ss;
        {
            float4 t = *(const float4*)&g_xm[((size_t)b*S_ + s)*INNER_ + 4*n];
            win[3][0]=t.x; win[3][1]=t.y; win[3][2]=t.z; win[3][3]=t.w;
        }
        float xa[4];
        #pragma unroll
        for (int o = 0; o < 4; o++) {
            float acc = cb[o];
            #pragma unroll
            for (int j = 0; j < 4; j++) acc += win[j][o] * cw[o][j];
            xa[o] = silu_f(acc);
        }
        float qv[4], kv4[4], vv[4];
        #pragma unroll
        for (int o = 0; o < 4; o++) {
            float a = 0.f, bk = 0.f, c2 = 0.f;
            #pragma unroll
            for (int i = 0; i < 4; i++) {
                a  += xa[i]     * qwr[o][i];
                bk += xa[i]     * kwr[o][i];
                c2 += win[3][i] * vwr[o][i];
            }
            qv[o] = a; kv4[o] = bk; vv[o] = c2;
        }
        size_t base = (((size_t)b*NH_ + h)*S_ + s)*DH_ + dbase;
        *(float4*)&g_q[base] = make_float4(qv[0],qv[1],qv[2],qv[3]);
        *(float4*)&g_k[base] = make_float4(kv4[0],kv4[1],kv4[2],kv4[3]);
        *(float4*)&g_v[base] = make_float4(vv[0],vv[1],vv[2],vv[3]);
        if (s == S_-1)
            *(float4*)&g_xa_last[b*INNER_ + 4*n] = make_float4(xa[0],xa[1],xa[2],xa[3]);

        #pragma unroll
        for (int o = 0; o < 4; o++) { win[0][o]=win[1][o]; win[1][o]=win[2][o]; win[2][o]=win[3][o]; }
    }
}

// ---------------- K3b: ig/fg gates: [qkv] dot 8 weight rows ----------------
// warp handles 8 consecutive t; lanes over channels; weights stay L1-resident
__global__ void k3b_gates(const float* __restrict__ igw, const float* __restrict__ igb,
                          const float* __restrict__ fgw, const float* __restrict__ fgb)
{
    int tid = threadIdx.x;
    int lane = tid & 31, w = tid >> 5;   // 8 warps
    int blk = blockIdx.x;                // 256 blocks
    int b = blk >> 3;
    int t0 = (blk & 7) * 64 + w * 8;

    float aI[8][4], aF[8][4];
    #pragma unroll
    for (int r = 0; r < 8; r++)
        #pragma unroll
        for (int g = 0; g < 4; g++) { aI[r][g] = 0.f; aF[r][g] = 0.f; }

    const float* segp[3] = { g_q, g_k, g_v };
    #pragma unroll
    for (int seg = 0; seg < 3; seg++) {
        const float* P = segp[seg];
        for (int c0 = 0; c0 < INNER_; c0 += 32) {
            int c = c0 + lane;
            int hh = c >> 8, dd = c & 255;
            float wI[4], wF[4];
            #pragma unroll
            for (int g = 0; g < 4; g++) {
                wI[g] = igw[g*3072 + seg*1024 + c];
                wF[g] = fgw[g*3072 + seg*1024 + c];
            }
            size_t rb = (((size_t)b*NH_ + hh)*S_ + t0)*DH_ + dd;
            #pragma unroll
            for (int r = 0; r < 8; r++) {
                float val = P[rb + (size_t)r*DH_];
                #pragma unroll
                for (int g = 0; g < 4; g++) { aI[r][g] += val*wI[g]; aF[r][g] += val*wF[g]; }
            }
        }
    }
    #pragma unroll
    for (int r = 0; r < 8; r++) {
        #pragma unroll
        for (int g = 0; g < 4; g++) {
            float sI = aI[r][g], sF = aF[r][g];
            #pragma unroll
            for (int o = 16; o > 0; o >>= 1) {
                sI += __shfl_xor_sync(0xffffffffu, sI, o);
                sF += __shfl_xor_sync(0xffffffffu, sF, o);
            }
            if (lane == 0) {
                int t = t0 + r;
                g_ig[(b*NH_+g)*S_ + t] = sI + igb[g];
                float fgv = sF + fgb[g];
                float lf = (fgv >= 0.f) ? -log1pf(expf(-fgv)) : (fgv - log1pf(expf(fgv)));
                g_lf[(b*NH_+g)*S_ + t] = lf;
            }
        }
    }
}

// ---------------- K4: mLSTM last-row + head-LN + hs ----------------
__global__ void k4_mlstm(const float* __restrict__ wup, const float* __restrict__ onormw,
                         const float* __restrict__ skipw)
{
    int tid = threadIdx.x;               // 256
    int lane = tid & 31, wrp = tid >> 5; // 8 warps
    int b = blockIdx.x >> 2, h = blockIdx.x & 3;
    size_t bh = (size_t)b*NH_ + h;

    __shared__ float s_q[DH_];
    __shared__ float s_w[S_];
    __shared__ float s_qk[S_];
    __shared__ float s_hr[E_];
    __shared__ float red[256];
    __shared__ float wtot[8], woff[8];

    s_q[tid] = g_q[(bh*S_ + (S_-1))*DH_ + tid];
    s_hr[tid]       = g_h[((size_t)b*S_ + (S_-1))*E_ + tid];
    s_hr[tid + 256] = g_h[((size_t)b*S_ + (S_-1))*E_ + tid + 256];

    int t0 = 2*tid, t1 = 2*tid + 1;
    float lf0 = g_lf[bh*S_ + t0], lf1 = g_lf[bh*S_ + t1];
    float ig0 = g_ig[bh*S_ + t0], ig1 = g_ig[bh*S_ + t1];

    // block inclusive scan of lf (2 elems/thread)
    float v = lf0 + lf1;
    #pragma unroll
    for (int o = 1; o < 32; o <<= 1) {
        float u = __shfl_up_sync(0xffffffffu, v, o);
        if (lane >= o) v += u;
    }
    if (lane == 31) wtot[wrp] = v;
    __syncthreads();
    if (tid < 8) { float t = 0.f; for (int i = 0; i < tid; i++) t += wtot[i]; woff[tid] = t; }
    __syncthreads();
    float cin  = v + woff[wrp];          // inclusive prefix through t1
    float c0   = cin - lf1;              // inclusive prefix through t0
    float total = woff[7] + wtot[7];
    float logd0 = (total - c0)  + ig0;
    float logd1 = (total - cin) + ig1;

    // block max
    red[tid] = fmaxf(logd0, logd1);
    __syncthreads();
    for (int o = 128; o > 0; o >>= 1) { if (tid < o) red[tid] = fmaxf(red[tid], red[tid+o]); __syncthreads(); }
    float maxd = red[0];
    __syncthreads();

    float d0 = expf(logd0 - maxd), d1 = expf(logd1 - maxd);
    s_w[t0] = d0; s_w[t1] = d1;
    __syncthreads();

    // qk[t] = (q_last . k_t) / 16  — warp per t
    const float* kb = g_k + bh*S_*DH_;
    for (int t = wrp; t < S_; t += 8) {
        const float* kr = kb + (size_t)t*DH_;
        float p = 0.f;
        #pragma unroll
        for (int d = lane; d < DH_; d += 32) p += s_q[d]*kr[d];
        #pragma unroll
        for (int o = 16; o > 0; o >>= 1) p += __shfl_xor_sync(0xffffffffu, p, o);
        if (lane == 0) s_qk[t] = p * 0.0625f;
    }
    __syncthreads();

    float cm0 = s_qk[t0]*d0, cm1 = s_qk[t1]*d1;
    red[tid] = cm0 + cm1;
    __syncthreads();
    for (int o = 128; o > 0; o >>= 1) { if (tid < o) red[tid] += red[tid+o]; __syncthreads(); }
    float csum = red[0];
    __syncthreads();
    float inv = 1.f / (fmaxf(fabsf(csum), expf(-maxd)) + 1e-6f);
    s_w[t0] = cm0*inv; s_w[t1] = cm1*inv;
    __syncthreads();

    // hc[d] = sum_t w[t]*v[t][d]
    const float* vb = g_v + bh*S_*DH_;
    float acc = 0.f;
    #pragma unroll 4
    for (int t = 0; t < S_; t++) acc += s_w[t]*vb[(size_t)t*DH_ + tid];

    // LN over DH (no weight)
    red[tid] = acc; __syncthreads();
    for (int o = 128; o > 0; o >>= 1) { if (tid < o) red[tid] += red[tid+o]; __syncthreads(); }
    float mu = red[0] * (1.f/DH_);
    __syncthreads();
    red[tid] = acc*acc; __syncthreads();
    for (int o = 128; o > 0; o >>= 1) { if (tid < o) red[tid] += red[tid+o]; __syncthreads(); }
    float var = red[0]*(1.f/DH_) - mu*mu;
    float hn = (acc - mu) * rsqrtf(var + 1e-5f);

    // z_last for this channel (w_up second half), then hs
    int c = h*DH_ + tid;
    const float* wz = wup + (size_t)(INNER_ + c)*E_;
    float z = 0.f;
    #pragma unroll 4
    for (int e = 0; e < E_; e++) z += s_hr[e]*wz[e];
    float hs = (hn*onormw[c] + skipw[c]*g_xa_last[b*INNER_ + c]) * silu_f(z);
    g_hs[b*INNER_ + c] = hs;
}

// ---------------- K5: down-proj (last pos) + post-LN + head ----------------
__global__ void k5_final(const float* __restrict__ wdown, const float* __restrict__ lnpw,
                         const float* __restrict__ fcw, const float* __restrict__ fcb,
                         float* __restrict__ out)
{
    int b = blockIdx.x;
    int tid = threadIdx.x;               // 512 threads, 16 warps
    int lane = tid & 31, wrp = tid >> 5;

    __shared__ float s_hs[INNER_];
    __shared__ float s_y[E_];
    __shared__ float red[512];

    s_hs[tid]       = g_hs[b*INNER_ + tid];
    s_hs[tid + 512] = g_hs[b*INNER_ + tid + 512];
    __syncthreads();

    for (int e = wrp; e < E_; e += 16) {
        const float* wr = wdown + (size_t)e*INNER_;
        float p = 0.f;
        #pragma unroll
        for (int c = lane; c < INNER_; c += 32) p += s_hs[c]*wr[c];
        #pragma unroll
        for (int o = 16; o > 0; o >>= 1) p += __shfl_xor_sync(0xffffffffu, p, o);
        if (lane == 0) s_y[e] = g_res_last[b*E_ + e] + p;
    }
    __syncthreads();

    float xv = s_y[tid];
    red[tid] = xv; __syncthreads();
    for (int o = 256; o > 0; o >>= 1) { if (tid < o) red[tid] += red[tid+o]; __syncthreads(); }
    float mean = red[0] * (1.f/E_);
    __syncthreads();
    red[tid] = xv*xv; __syncthreads();
    for (int o = 256; o > 0; o >>= 1) { if (tid < o) red[tid] += red[tid+o]; __syncthreads(); }
    float var = red[0]*(1.f/E_) - mean*mean;
    float xf = (xv - mean) * rsqrtf(var + 1e-5f) * lnpw[tid];
    __syncthreads();
    red[tid] = xf * fcw[tid]; __syncthreads();
    for (int o = 256; o > 0; o >>= 1) { if (tid < o) red[tid] += red[tid+o]; __syncthreads(); }
    if (tid == 0) out[b] = 1.f / (1.f + expf(-(red[0] + fcb[0])));
}

// ---------------- launch ----------------
extern "C" void kernel_launch(void* const* d_in, const int* in_sizes, int n_in,
                              void* d_out, int out_size)
{
    const int*   tokens = (const int*)  d_in[0];
    const float* emb    = (const float*)d_in[1];
    const float* ln1w   = (const float*)d_in[2];
    const float* convw  = (const float*)d_in[3];
    const float* convb  = (const float*)d_in[4];
    const float* wup    = (const float*)d_in[5];
    const float* qw     = (const float*)d_in[6];
    const float* kw     = (const float*)d_in[7];
    const float* vw     = (const float*)d_in[8];
    const float* igw    = (const float*)d_in[9];
    const float* igb    = (const float*)d_in[10];
    const float* fgw    = (const float*)d_in[11];
    const float* fgb    = (const float*)d_in[12];
    const float* onormw = (const float*)d_in[13];
    const float* skipw  = (const float*)d_in[14];
    const float* wdown  = (const float*)d_in[15];
    const float* lnpw   = (const float*)d_in[16];
    const float* fcw    = (const float*)d_in[17];
    const float* fcb    = (const float*)d_in[18];
    float* out = (float*)d_out;

    k1_embed_ln<<<M_TOK, 256>>>(tokens, emb, ln1w);
    dim3 g2(INNER_/BN, M_TOK/BM);
    k2_gemm_up<<<g2, 256>>>(wup);
    dim3 g3(S_/8, B_);
    k3_conv_qkv<<<g3, 256>>>(convw, convb, qw, kw, vw);
    k3b_gates<<<256, 256>>>(igw, igb, fgw, fgb);
    k4_mlstm<<<B_*NH_, 256>>>(wup, onormw, skipw);
    k5_final<<<B_, 512>>>(wdown, lnpw, fcw, fcb, out);
}

// round 3
// speedup vs baseline: 1.5367x; 1.5367x over previous
#include <cuda_runtime.h>
#include <math.h>
#include <stddef.h>
#include <stdint.h>

#define B_   32
#define S_   512
#define E_   512
#define INNER_ 1024
#define NH_  4
#define DH_  256
#define M_TOK (B_*S_)   // 16384

// ---------------- scratch (device globals: allocation-free) ----------------
__device__ float g_h[(size_t)M_TOK*E_];          // LN'd embeddings      (32 MB)
__device__ float g_xm[(size_t)M_TOK*INNER_];     // up-proj first half   (64 MB)
__device__ float g_q[(size_t)B_*NH_*S_*DH_];     // q  [b][h][t][d]      (64 MB)
__device__ float g_k[(size_t)B_*NH_*S_*DH_];     // k                    (64 MB)
__device__ float g_v[(size_t)B_*NH_*S_*DH_];     // v                    (64 MB)
__device__ float g_ig[B_*NH_*S_];
__device__ float g_lf[B_*NH_*S_];                // log_sigmoid(fg)
__device__ float g_res_last[B_*E_];
__device__ float g_xa_last[B_*INNER_];
__device__ float g_hs[B_*INNER_];

__device__ __forceinline__ float silu_f(float x) { return x / (1.f + expf(-x)); }

__device__ __forceinline__ uint32_t f2tf32(float f) {
    uint32_t u;
    asm("cvt.rna.tf32.f32 %0, %1;" : "=r"(u) : "f"(f));
    return u;
}

// ---------------- K1: embedding gather + LayerNorm ----------------
__global__ void k1_embed_ln(const int* __restrict__ tokens,
                            const float* __restrict__ emb,
                            const float* __restrict__ ln1w)
{
    int m = blockIdx.x;
    int tid = threadIdx.x;           // 256 threads, 2 elems each
    int tok = tokens[m];
    float x0 = 0.f, x1 = 0.f;
    if (tok != 0) {                  // emb.at[0].set(0)
        const float* row = emb + (size_t)tok * E_;
        x0 = row[tid];
        x1 = row[tid + 256];
    }
    __shared__ float red[256];
    red[tid] = x0 + x1;
    __syncthreads();
    for (int o = 128; o > 0; o >>= 1) { if (tid < o) red[tid] += red[tid+o]; __syncthreads(); }
    float mean = red[0] * (1.f / E_);
    __syncthreads();
    red[tid] = x0*x0 + x1*x1;
    __syncthreads();
    for (int o = 128; o > 0; o >>= 1) { if (tid < o) red[tid] += red[tid+o]; __syncthreads(); }
    float var = red[0] * (1.f / E_) - mean*mean;
    float rstd = rsqrtf(var + 1e-5f);

    g_h[(size_t)m*E_ + tid]       = (x0 - mean) * rstd * ln1w[tid];
    g_h[(size_t)m*E_ + tid + 256] = (x1 - mean) * rstd * ln1w[tid + 256];

    if ((m & (S_-1)) == S_-1) {
        int b = m >> 9;
        g_res_last[b*E_ + tid]       = x0;
        g_res_last[b*E_ + tid + 256] = x1;
    }
}

// ---------------- K2: up-projection GEMM via tf32 tensor cores ----------------
// C[m,n] = sum_k g_h[m,k] * wup[n,k],  M=16384, N=1024(first half), K=512
// block tile 128x128x16, 256 threads = 8 warps (2x4), warp tile 64x32
#define TBM 128
#define TBN 128
#define TBK 16
#define NIT (E_/TBK)   // 32

__global__ void __launch_bounds__(256, 2) k2_gemm_up(const float* __restrict__ wup)
{
    __shared__ uint32_t As[2][TBM][20];   // [m][k] tf32, stride 20 (conflict-free)
    __shared__ uint32_t Bs[2][TBN][20];   // [n][k] tf32

    int tid  = threadIdx.x;
    int lane = tid & 31;
    int wid  = tid >> 5;
    int warp_m = wid & 1;          // 0..1
    int warp_n = wid >> 1;         // 0..3
    int g  = lane >> 2;            // groupID
    int tg = lane & 3;             // threadID in group

    int m0 = blockIdx.y * TBM;
    int n0 = blockIdx.x * TBN;

    // global load indices: 2 float4 per thread per tile
    int ar0 = tid >> 2,        af0 = (tid & 3) * 4;
    int ar1 = ar0 + 64,        af1 = af0;

    float c[4][4][4];
    #pragma unroll
    for (int mt = 0; mt < 4; mt++)
        #pragma unroll
        for (int nt = 0; nt < 4; nt++)
            #pragma unroll
            for (int r = 0; r < 4; r++) c[mt][nt][r] = 0.f;

    // prefetch tile 0
    float4 apf0 = *(const float4*)&g_h[(size_t)(m0+ar0)*E_ + af0];
    float4 apf1 = *(const float4*)&g_h[(size_t)(m0+ar1)*E_ + af1];
    float4 bpf0 = *(const float4*)&wup[(size_t)(n0+ar0)*E_ + af0];
    float4 bpf1 = *(const float4*)&wup[(size_t)(n0+ar1)*E_ + af1];
    As[0][ar0][af0+0]=f2tf32(apf0.x); As[0][ar0][af0+1]=f2tf32(apf0.y);
    As[0][ar0][af0+2]=f2tf32(apf0.z); As[0][ar0][af0+3]=f2tf32(apf0.w);
    As[0][ar1][af1+0]=f2tf32(apf1.x); As[0][ar1][af1+1]=f2tf32(apf1.y);
    As[0][ar1][af1+2]=f2tf32(apf1.z); As[0][ar1][af1+3]=f2tf32(apf1.w);
    Bs[0][ar0][af0+0]=f2tf32(bpf0.x); Bs[0][ar0][af0+1]=f2tf32(bpf0.y);
    Bs[0][ar0][af0+2]=f2tf32(bpf0.z); Bs[0][ar0][af0+3]=f2tf32(bpf0.w);
    Bs[0][ar1][af1+0]=f2tf32(bpf1.x); Bs[0][ar1][af1+1]=f2tf32(bpf1.y);
    Bs[0][ar1][af1+2]=f2tf32(bpf1.z); Bs[0][ar1][af1+3]=f2tf32(bpf1.w);
    __syncthreads();

    for (int it = 0; it < NIT; it++) {
        int buf = it & 1;
        int nxt = it + 1;
        if (nxt < NIT) {
            int k0 = nxt * TBK;
            apf0 = *(const float4*)&g_h[(size_t)(m0+ar0)*E_ + k0 + af0];
            apf1 = *(const float4*)&g_h[(size_t)(m0+ar1)*E_ + k0 + af1];
            bpf0 = *(const float4*)&wup[(size_t)(n0+ar0)*E_ + k0 + af0];
            bpf1 = *(const float4*)&wup[(size_t)(n0+ar1)*E_ + k0 + af1];
        }
        #pragma unroll
        for (int ks = 0; ks < 2; ks++) {
            int kb = ks * 8;
            uint32_t af[4][4], bf[4][2];
            #pragma unroll
            for (int mt = 0; mt < 4; mt++) {
                int row = warp_m*64 + mt*16 + g;
                af[mt][0] = As[buf][row  ][kb+tg];
                af[mt][1] = As[buf][row+8][kb+tg];
                af[mt][2] = As[buf][row  ][kb+tg+4];
                af[mt][3] = As[buf][row+8][kb+tg+4];
            }
            #pragma unroll
            for (int nt = 0; nt < 4; nt++) {
                int n = warp_n*32 + nt*8 + g;
                bf[nt][0] = Bs[buf][n][kb+tg];
                bf[nt][1] = Bs[buf][n][kb+tg+4];
            }
            #pragma unroll
            for (int mt = 0; mt < 4; mt++)
                #pragma unroll
                for (int nt = 0; nt < 4; nt++) {
                    asm volatile(
                        "mma.sync.aligned.m16n8k8.row.col.f32.tf32.tf32.f32 "
                        "{%0,%1,%2,%3}, {%4,%5,%6,%7}, {%8,%9}, {%0,%1,%2,%3};"
                        : "+f"(c[mt][nt][0]), "+f"(c[mt][nt][1]),
                          "+f"(c[mt][nt][2]), "+f"(c[mt][nt][3])
                        : "r"(af[mt][0]), "r"(af[mt][1]), "r"(af[mt][2]), "r"(af[mt][3]),
                          "r"(bf[nt][0]), "r"(bf[nt][1]));
                }
        }
        if (nxt < NIT) {
            int nb = nxt & 1;
            As[nb][ar0][af0+0]=f2tf32(apf0.x); As[nb][ar0][af0+1]=f2tf32(apf0.y);
            As[nb][ar0][af0+2]=f2tf32(apf0.z); As[nb][ar0][af0+3]=f2tf32(apf0.w);
            As[nb][ar1][af1+0]=f2tf32(apf1.x); As[nb][ar1][af1+1]=f2tf32(apf1.y);
            As[nb][ar1][af1+2]=f2tf32(apf1.z); As[nb][ar1][af1+3]=f2tf32(apf1.w);
            Bs[nb][ar0][af0+0]=f2tf32(bpf0.x); Bs[nb][ar0][af0+1]=f2tf32(bpf0.y);
            Bs[nb][ar0][af0+2]=f2tf32(bpf0.z); Bs[nb][ar0][af0+3]=f2tf32(bpf0.w);
            Bs[nb][ar1][af1+0]=f2tf32(bpf1.x); Bs[nb][ar1][af1+1]=f2tf32(bpf1.y);
            Bs[nb][ar1][af1+2]=f2tf32(bpf1.z); Bs[nb][ar1][af1+3]=f2tf32(bpf1.w);
        }
        __syncthreads();
    }

    // epilogue: write C tiles
    #pragma unroll
    for (int mt = 0; mt < 4; mt++) {
        int row = m0 + warp_m*64 + mt*16 + g;
        #pragma unroll
        for (int nt = 0; nt < 4; nt++) {
            int col = n0 + warp_n*32 + nt*8 + 2*tg;
            *(float2*)&g_xm[(size_t)row*INNER_ + col]     = make_float2(c[mt][nt][0], c[mt][nt][1]);
            *(float2*)&g_xm[(size_t)(row+8)*INNER_ + col] = make_float2(c[mt][nt][2], c[mt][nt][3]);
        }
    }
}

// ---------------- K3: causal conv + silu + block-diag q/k/v ----------------
__global__ void k3_conv_qkv(const float* __restrict__ convw, const float* __restrict__ convb,
                            const float* __restrict__ qw, const float* __restrict__ kw,
                            const float* __restrict__ vw)
{
    int n  = threadIdx.x;
    int b  = blockIdx.y;
    int s0 = blockIdx.x * 8;

    float cw[4][4], cb[4], qwr[4][4], kwr[4][4], vwr[4][4];
    #pragma unroll
    for (int o = 0; o < 4; o++) {
        cb[o] = convb[4*n + o];
        #pragma unroll
        for (int j = 0; j < 4; j++) cw[o][j] = convw[(4*n+o)*4 + j];
        #pragma unroll
        for (int i = 0; i < 4; i++) {
            qwr[o][i] = qw[(n*4+o)*4 + i];
            kwr[o][i] = kw[(n*4+o)*4 + i];
            vwr[o][i] = vw[(n*4+o)*4 + i];
        }
    }

    float win[4][4];                 // win[j] = x_m at s-3+j
    #pragma unroll
    for (int j = 0; j < 3; j++) {
        int s = s0 - 3 + j;
        if (s >= 0) {
            float4 t = *(const float4*)&g_xm[((size_t)b*S_ + s)*INNER_ + 4*n];
            win[j][0]=t.x; win[j][1]=t.y; win[j][2]=t.z; win[j][3]=t.w;
        } else {
            win[j][0]=win[j][1]=win[j][2]=win[j][3]=0.f;
        }
    }
    int h = n >> 6;
    int dbase = (n & 63) * 4;

    for (int ss = 0; ss < 8; ss++) {
        int s = s0 + ss;
        {
            float4 t = *(const float4*)&g_xm[((size_t)b*S_ + s)*INNER_ + 4*n];
            win[3][0]=t.x; win[3][1]=t.y; win[3][2]=t.z; win[3][3]=t.w;
        }
        float xa[4];
        #pragma unroll
        for (int o = 0; o < 4; o++) {
            float acc = cb[o];
            #pragma unroll
            for (int j = 0; j < 4; j++) acc += win[j][o] * cw[o][j];
            xa[o] = silu_f(acc);
        }
        float qv[4], kv4[4], vv[4];
        #pragma unroll
        for (int o = 0; o < 4; o++) {
            float a = 0.f, bk = 0.f, c2 = 0.f;
            #pragma unroll
            for (int i = 0; i < 4; i++) {
                a  += xa[i]     * qwr[o][i];
                bk += xa[i]     * kwr[o][i];
                c2 += win[3][i] * vwr[o][i];
            }
            qv[o] = a; kv4[o] = bk; vv[o] = c2;
        }
        size_t base = (((size_t)b*NH_ + h)*S_ + s)*DH_ + dbase;
        *(float4*)&g_q[base] = make_float4(qv[0],qv[1],qv[2],qv[3]);
        *(float4*)&g_k[base] = make_float4(kv4[0],kv4[1],kv4[2],kv4[3]);
        *(float4*)&g_v[base] = make_float4(vv[0],vv[1],vv[2],vv[3]);
        if (s == S_-1)
            *(float4*)&g_xa_last[b*INNER_ + 4*n] = make_float4(xa[0],xa[1],xa[2],xa[3]);

        #pragma unroll
        for (int o = 0; o < 4; o++) { win[0][o]=win[1][o]; win[1][o]=win[2][o]; win[2][o]=win[3][o]; }
    }
}

// ---------------- K3b: ig/fg gates (4 t-rows per warp, 512 blocks) ----------------
__global__ void k3b_gates(const float* __restrict__ igw, const float* __restrict__ igb,
                          const float* __restrict__ fgw, const float* __restrict__ fgb)
{
    int tid = threadIdx.x;
    int lane = tid & 31, w = tid >> 5;   // 8 warps
    int blk = blockIdx.x;                // 512 blocks
    int b = blk >> 4;
    int t0 = (blk & 15) * 32 + w * 4;

    float aI[4][4], aF[4][4];
    #pragma unroll
    for (int r = 0; r < 4; r++)
        #pragma unroll
        for (int g = 0; g < 4; g++) { aI[r][g] = 0.f; aF[r][g] = 0.f; }

    const float* segp[3] = { g_q, g_k, g_v };
    #pragma unroll
    for (int seg = 0; seg < 3; seg++) {
        const float* P = segp[seg];
        for (int c0 = 0; c0 < INNER_; c0 += 32) {
            int c = c0 + lane;
            int hh = c >> 8, dd = c & 255;
            float wI[4], wF[4];
            #pragma unroll
            for (int g = 0; g < 4; g++) {
                wI[g] = igw[g*3072 + seg*1024 + c];
                wF[g] = fgw[g*3072 + seg*1024 + c];
            }
            size_t rb = (((size_t)b*NH_ + hh)*S_ + t0)*DH_ + dd;
            #pragma unroll
            for (int r = 0; r < 4; r++) {
                float val = P[rb + (size_t)r*DH_];
                #pragma unroll
                for (int g = 0; g < 4; g++) { aI[r][g] += val*wI[g]; aF[r][g] += val*wF[g]; }
            }
        }
    }
    #pragma unroll
    for (int r = 0; r < 4; r++) {
        #pragma unroll
        for (int g = 0; g < 4; g++) {
            float sI = aI[r][g], sF = aF[r][g];
            #pragma unroll
            for (int o = 16; o > 0; o >>= 1) {
                sI += __shfl_xor_sync(0xffffffffu, sI, o);
                sF += __shfl_xor_sync(0xffffffffu, sF, o);
            }
            if (lane == 0) {
                int t = t0 + r;
                g_ig[(b*NH_+g)*S_ + t] = sI + igb[g];
                float fgv = sF + fgb[g];
                float lf = (fgv >= 0.f) ? -log1pf(expf(-fgv)) : (fgv - log1pf(expf(fgv)));
                g_lf[(b*NH_+g)*S_ + t] = lf;
            }
        }
    }
}

// ---------------- K4: mLSTM last-row + head-LN + hs ----------------
__global__ void k4_mlstm(const float* __restrict__ wup, const float* __restrict__ onormw,
                         const float* __restrict__ skipw)
{
    int tid = threadIdx.x;               // 256
    int lane = tid & 31, wrp = tid >> 5; // 8 warps
    int b = blockIdx.x >> 2, h = blockIdx.x & 3;
    size_t bh = (size_t)b*NH_ + h;

    __shared__ float s_q[DH_];
    __shared__ float s_w[S_];
    __shared__ float s_qk[S_];
    __shared__ float s_hr[E_];
    __shared__ float s_z[DH_];
    __shared__ float red[256];
    __shared__ float wtot[8], woff[8];

    s_q[tid] = g_q[(bh*S_ + (S_-1))*DH_ + tid];
    s_hr[tid]       = g_h[((size_t)b*S_ + (S_-1))*E_ + tid];
    s_hr[tid + 256] = g_h[((size_t)b*S_ + (S_-1))*E_ + tid + 256];

    int t0 = 2*tid, t1 = 2*tid + 1;
    float lf0 = g_lf[bh*S_ + t0], lf1 = g_lf[bh*S_ + t1];
    float ig0 = g_ig[bh*S_ + t0], ig1 = g_ig[bh*S_ + t1];

    // block inclusive scan of lf (2 elems/thread)
    float v = lf0 + lf1;
    #pragma unroll
    for (int o = 1; o < 32; o <<= 1) {
        float u = __shfl_up_sync(0xffffffffu, v, o);
        if (lane >= o) v += u;
    }
    if (lane == 31) wtot[wrp] = v;
    __syncthreads();
    if (tid < 8) { float t = 0.f; for (int i = 0; i < tid; i++) t += wtot[i]; woff[tid] = t; }
    __syncthreads();
    float cin  = v + woff[wrp];          // inclusive prefix through t1
    float c0   = cin - lf1;              // inclusive prefix through t0
    float total = woff[7] + wtot[7];
    float logd0 = (total - c0)  + ig0;
    float logd1 = (total - cin) + ig1;

    // block max
    red[tid] = fmaxf(logd0, logd1);
    __syncthreads();
    for (int o = 128; o > 0; o >>= 1) { if (tid < o) red[tid] = fmaxf(red[tid], red[tid+o]); __syncthreads(); }
    float maxd = red[0];
    __syncthreads();

    float d0 = expf(logd0 - maxd), d1 = expf(logd1 - maxd);
    s_w[t0] = d0; s_w[t1] = d1;
    __syncthreads();

    // qk[t] = (q_last . k_t) / 16  — warp per t
    const float* kb = g_k + bh*S_*DH_;
    for (int t = wrp; t < S_; t += 8) {
        const float* kr = kb + (size_t)t*DH_;
        float p = 0.f;
        #pragma unroll
        for (int d = lane; d < DH_; d += 32) p += s_q[d]*kr[d];
        #pragma unroll
        for (int o = 16; o > 0; o >>= 1) p += __shfl_xor_sync(0xffffffffu, p, o);
        if (lane == 0) s_qk[t] = p * 0.0625f;
    }
    __syncthreads();

    float cm0 = s_qk[t0]*d0, cm1 = s_qk[t1]*d1;
    red[tid] = cm0 + cm1;
    __syncthreads();
    for (int o = 128; o > 0; o >>= 1) { if (tid < o) red[tid] += red[tid+o]; __syncthreads(); }
    float csum = red[0];
    __syncthreads();
    float inv = 1.f / (fmaxf(fabsf(csum), expf(-maxd)) + 1e-6f);
    s_w[t0] = cm0*inv; s_w[t1] = cm1*inv;
    __syncthreads();

    // z_last via warp-cooperative coalesced dot products: warp wrp owns
    // channels cl = wrp*32 .. wrp*32+31 (within this head's 256)
    for (int j = 0; j < 32; j++) {
        int cl = wrp*32 + j;
        const float* wz = wup + (size_t)(INNER_ + h*DH_ + cl)*E_;
        float p = 0.f;
        #pragma unroll
        for (int i = 0; i < 4; i++) {
            float4 t = *(const float4*)&wz[lane*4 + i*128];
            int e = lane*4 + i*128;
            p += s_hr[e]*t.x + s_hr[e+1]*t.y + s_hr[e+2]*t.z + s_hr[e+3]*t.w;
        }
        #pragma unroll
        for (int o = 16; o > 0; o >>= 1) p += __shfl_xor_sync(0xffffffffu, p, o);
        if (lane == 0) s_z[cl] = p;
    }

    // hc[d] = sum_t w[t]*v[t][d]
    const float* vb = g_v + bh*S_*DH_;
    float acc = 0.f;
    #pragma unroll 4
    for (int t = 0; t < S_; t++) acc += s_w[t]*vb[(size_t)t*DH_ + tid];

    // LN over DH (no weight)
    red[tid] = acc; __syncthreads();
    for (int o = 128; o > 0; o >>= 1) { if (tid < o) red[tid] += red[tid+o]; __syncthreads(); }
    float mu = red[0] * (1.f/DH_);
    __syncthreads();
    red[tid] = acc*acc; __syncthreads();
    for (int o = 128; o > 0; o >>= 1) { if (tid < o) red[tid] += red[tid+o]; __syncthreads(); }
    float var = red[0]*(1.f/DH_) - mu*mu;
    float hn = (acc - mu) * rsqrtf(var + 1e-5f);

    int c = h*DH_ + tid;
    float z = s_z[tid];
    float hs = (hn*onormw[c] + skipw[c]*g_xa_last[b*INNER_ + c]) * silu_f(z);
    g_hs[b*INNER_ + c] = hs;
}

// ---------------- K5: down-proj (last pos) + post-LN + head ----------------
__global__ void k5_final(const float* __restrict__ wdown, const float* __restrict__ lnpw,
                         const float* __restrict__ fcw, const float* __restrict__ fcb,
                         float* __restrict__ out)
{
    int b = blockIdx.x;
    int tid = threadIdx.x;               // 512 threads, 16 warps
    int lane = tid & 31, wrp = tid >> 5;

    __shared__ float s_hs[INNER_];
    __shared__ float s_y[E_];
    __shared__ float red[512];

    s_hs[tid]       = g_hs[b*INNER_ + tid];
    s_hs[tid + 512] = g_hs[b*INNER_ + tid + 512];
    __syncthreads();

    for (int e = wrp; e < E_; e += 16) {
        const float* wr = wdown + (size_t)e*INNER_;
        float p = 0.f;
        #pragma unroll
        for (int c = lane; c < INNER_; c += 32) p += s_hs[c]*wr[c];
        #pragma unroll
        for (int o = 16; o > 0; o >>= 1) p += __shfl_xor_sync(0xffffffffu, p, o);
        if (lane == 0) s_y[e] = g_res_last[b*E_ + e] + p;
    }
    __syncthreads();

    float xv = s_y[tid];
    red[tid] = xv; __syncthreads();
    for (int o = 256; o > 0; o >>= 1) { if (tid < o) red[tid] += red[tid+o]; __syncthreads(); }
    float mean = red[0] * (1.f/E_);
    __syncthreads();
    red[tid] = xv*xv; __syncthreads();
    for (int o = 256; o > 0; o >>= 1) { if (tid < o) red[tid] += red[tid+o]; __syncthreads(); }
    float var = red[0]*(1.f/E_) - mean*mean;
    float xf = (xv - mean) * rsqrtf(var + 1e-5f) * lnpw[tid];
    __syncthreads();
    red[tid] = xf * fcw[tid]; __syncthreads();
    for (int o = 256; o > 0; o >>= 1) { if (tid < o) red[tid] += red[tid+o]; __syncthreads(); }
    if (tid == 0) out[b] = 1.f / (1.f + expf(-(red[0] + fcb[0])));
}

// ---------------- launch ----------------
extern "C" void kernel_launch(void* const* d_in, const int* in_sizes, int n_in,
                              void* d_out, int out_size)
{
    const int*   tokens = (const int*)  d_in[0];
    const float* emb    = (const float*)d_in[1];
    const float* ln1w   = (const float*)d_in[2];
    const float* convw  = (const float*)d_in[3];
    const float* convb  = (const float*)d_in[4];
    const float* wup    = (const float*)d_in[5];
    const float* qw     = (const float*)d_in[6];
    const float* kw     = (const float*)d_in[7];
    const float* vw     = (const float*)d_in[8];
    const float* igw    = (const float*)d_in[9];
    const float* igb    = (const float*)d_in[10];
    const float* fgw    = (const float*)d_in[11];
    const float* fgb    = (const float*)d_in[12];
    const float* onormw = (const float*)d_in[13];
    const float* skipw  = (const float*)d_in[14];
    const float* wdown  = (const float*)d_in[15];
    const float* lnpw   = (const float*)d_in[16];
    const float* fcw    = (const float*)d_in[17];
    const float* fcb    = (const float*)d_in[18];
    float* out = (float*)d_out;

    k1_embed_ln<<<M_TOK, 256>>>(tokens, emb, ln1w);
    dim3 g2(INNER_/TBN, M_TOK/TBM);
    k2_gemm_up<<<g2, 256>>>(wup);
    dim3 g3(S_/8, B_);
    k3_conv_qkv<<<g3, 256>>>(convw, convb, qw, kw, vw);
    k3b_gates<<<512, 256>>>(igw, igb, fgw, fgb);
    k4_mlstm<<<B_*NH_, 256>>>(wup, onormw, skipw);
    k5_final<<<B_, 512>>>(wdown, lnpw, fcw, fcb, out);
}

// round 4
// speedup vs baseline: 1.7325x; 1.1274x over previous
#include <cuda_runtime.h>
#include <math.h>
#include <stddef.h>
#include <stdint.h>

#define B_   32
#define S_   512
#define E_   512
#define INNER_ 1024
#define NH_  4
#define DH_  256
#define M_TOK (B_*S_)   // 16384

// ---------------- scratch (device globals: allocation-free) ----------------
__device__ float g_h[(size_t)M_TOK*E_];          // LN'd embeddings, tf32-rounded (32 MB)
__device__ float g_wt[(size_t)INNER_*E_];        // w_up first half, tf32-rounded (2 MB)
__device__ float g_xm[(size_t)M_TOK*INNER_];     // up-proj first half   (64 MB)
__device__ float g_q[(size_t)B_*NH_*S_*DH_];     // q  [b][h][t][d]      (64 MB)
__device__ float g_k[(size_t)B_*NH_*S_*DH_];     // k                    (64 MB)
__device__ float g_v[(size_t)B_*NH_*S_*DH_];     // v                    (64 MB)
__device__ float g_ig[B_*NH_*S_];
__device__ float g_lf[B_*NH_*S_];                // log_sigmoid(fg)
__device__ float g_res_last[B_*E_];
__device__ float g_xa_last[B_*INNER_];
__device__ float g_hs[B_*INNER_];

__device__ __forceinline__ float silu_f(float x) { return x / (1.f + expf(-x)); }

__device__ __forceinline__ float f2tf32f(float f) {
    uint32_t u;
    asm("cvt.rna.tf32.f32 %0, %1;" : "=r"(u) : "f"(f));
    return __uint_as_float(u);
}

__device__ __forceinline__ void cp16(void* smem, const void* gmem) {
    uint32_t s = (uint32_t)__cvta_generic_to_shared(smem);
    asm volatile("cp.async.cg.shared.global [%0], [%1], 16;" :: "r"(s), "l"(gmem));
}

// ---------------- K0: pre-round w_up first half to tf32 ----------------
__global__ void k0_round_wup(const float* __restrict__ wup)
{
    int i = (blockIdx.x * 256 + threadIdx.x) * 4;   // over INNER_*E_ = 524288
    float4 t = *(const float4*)&wup[i];
    t.x = f2tf32f(t.x); t.y = f2tf32f(t.y); t.z = f2tf32f(t.z); t.w = f2tf32f(t.w);
    *(float4*)&g_wt[i] = t;
}

// ---------------- K1: embedding gather + LayerNorm (tf32-rounded out) ----------------
__global__ void k1_embed_ln(const int* __restrict__ tokens,
                            const float* __restrict__ emb,
                            const float* __restrict__ ln1w)
{
    int m = blockIdx.x;
    int tid = threadIdx.x;           // 256 threads, 2 elems each
    int tok = tokens[m];
    float x0 = 0.f, x1 = 0.f;
    if (tok != 0) {                  // emb.at[0].set(0)
        const float* row = emb + (size_t)tok * E_;
        x0 = row[tid];
        x1 = row[tid + 256];
    }
    __shared__ float red[256];
    red[tid] = x0 + x1;
    __syncthreads();
    for (int o = 128; o > 0; o >>= 1) { if (tid < o) red[tid] += red[tid+o]; __syncthreads(); }
    float mean = red[0] * (1.f / E_);
    __syncthreads();
    red[tid] = x0*x0 + x1*x1;
    __syncthreads();
    for (int o = 128; o > 0; o >>= 1) { if (tid < o) red[tid] += red[tid+o]; __syncthreads(); }
    float var = red[0] * (1.f / E_) - mean*mean;
    float rstd = rsqrtf(var + 1e-5f);

    g_h[(size_t)m*E_ + tid]       = f2tf32f((x0 - mean) * rstd * ln1w[tid]);
    g_h[(size_t)m*E_ + tid + 256] = f2tf32f((x1 - mean) * rstd * ln1w[tid + 256]);

    if ((m & (S_-1)) == S_-1) {
        int b = m >> 9;
        g_res_last[b*E_ + tid]       = x0;
        g_res_last[b*E_ + tid + 256] = x1;
    }
}

// ---------------- K2: up-projection GEMM via tf32 tensor cores + cp.async ----------------
// C[m,n] = sum_k g_h[m,k] * g_wt[n,k],  M=16384, N=1024, K=512
#define TBM 128
#define TBN 128
#define TBK 16
#define NIT (E_/TBK)   // 32
#define STAGES 3
#define APITCH 20
#define TILE_U32 (TBM*APITCH)   // 2560
#define K2_SMEM (STAGES*2*TILE_U32*4)  // 61440 bytes

__global__ void __launch_bounds__(256) k2_gemm_up()
{
    extern __shared__ float sm[];
    float* As = sm;                        // [STAGES][TBM][20]
    float* Bs = sm + STAGES*TILE_U32;      // [STAGES][TBN][20]

    int tid  = threadIdx.x;
    int lane = tid & 31;
    int wid  = tid >> 5;
    int warp_m = wid & 1;          // 0..1
    int warp_n = wid >> 1;         // 0..3
    int g  = lane >> 2;            // groupID
    int tg = lane & 3;             // threadID in group

    int m0 = blockIdx.y * TBM;
    int n0 = blockIdx.x * TBN;

    int ar0 = tid >> 2,  af0 = (tid & 3) * 4;
    int ar1 = ar0 + 64;

    float c[4][4][4];
    #pragma unroll
    for (int mt = 0; mt < 4; mt++)
        #pragma unroll
        for (int nt = 0; nt < 4; nt++)
            #pragma unroll
            for (int r = 0; r < 4; r++) c[mt][nt][r] = 0.f;

    // prologue: issue tiles 0..STAGES-2
    #pragma unroll
    for (int p = 0; p < STAGES-1; p++) {
        int k0 = p * TBK;
        cp16(&As[p*TILE_U32 + ar0*APITCH + af0], &g_h[(size_t)(m0+ar0)*E_ + k0 + af0]);
        cp16(&As[p*TILE_U32 + ar1*APITCH + af0], &g_h[(size_t)(m0+ar1)*E_ + k0 + af0]);
        cp16(&Bs[p*TILE_U32 + ar0*APITCH + af0], &g_wt[(size_t)(n0+ar0)*E_ + k0 + af0]);
        cp16(&Bs[p*TILE_U32 + ar1*APITCH + af0], &g_wt[(size_t)(n0+ar1)*E_ + k0 + af0]);
        asm volatile("cp.async.commit_group;");
    }

    for (int it = 0; it < NIT; it++) {
        int pf = it + STAGES - 1;
        if (pf < NIT) {
            int st = pf % STAGES;
            int k0 = pf * TBK;
            cp16(&As[st*TILE_U32 + ar0*APITCH + af0], &g_h[(size_t)(m0+ar0)*E_ + k0 + af0]);
            cp16(&As[st*TILE_U32 + ar1*APITCH + af0], &g_h[(size_t)(m0+ar1)*E_ + k0 + af0]);
            cp16(&Bs[st*TILE_U32 + ar0*APITCH + af0], &g_wt[(size_t)(n0+ar0)*E_ + k0 + af0]);
            cp16(&Bs[st*TILE_U32 + ar1*APITCH + af0], &g_wt[(size_t)(n0+ar1)*E_ + k0 + af0]);
        }
        asm volatile("cp.async.commit_group;");   // uniform (possibly empty) group
        asm volatile("cp.async.wait_group %0;" :: "n"(STAGES-1));
        __syncthreads();

        const float* Ab = &As[(it % STAGES)*TILE_U32];
        const float* Bb = &Bs[(it % STAGES)*TILE_U32];
        #pragma unroll
        for (int ks = 0; ks < 2; ks++) {
            int kb = ks * 8;
            uint32_t af[4][4], bf[4][2];
            #pragma unroll
            for (int mt = 0; mt < 4; mt++) {
                int row = warp_m*64 + mt*16 + g;
                af[mt][0] = __float_as_uint(Ab[row*APITCH + kb+tg]);
                af[mt][1] = __float_as_uint(Ab[(row+8)*APITCH + kb+tg]);
                af[mt][2] = __float_as_uint(Ab[row*APITCH + kb+tg+4]);
                af[mt][3] = __float_as_uint(Ab[(row+8)*APITCH + kb+tg+4]);
            }
            #pragma unroll
            for (int nt = 0; nt < 4; nt++) {
                int n = warp_n*32 + nt*8 + g;
                bf[nt][0] = __float_as_uint(Bb[n*APITCH + kb+tg]);
                bf[nt][1] = __float_as_uint(Bb[n*APITCH + kb+tg+4]);
            }
            #pragma unroll
            for (int mt = 0; mt < 4; mt++)
                #pragma unroll
                for (int nt = 0; nt < 4; nt++) {
                    asm volatile(
                        "mma.sync.aligned.m16n8k8.row.col.f32.tf32.tf32.f32 "
                        "{%0,%1,%2,%3}, {%4,%5,%6,%7}, {%8,%9}, {%0,%1,%2,%3};"
                        : "+f"(c[mt][nt][0]), "+f"(c[mt][nt][1]),
                          "+f"(c[mt][nt][2]), "+f"(c[mt][nt][3])
                        : "r"(af[mt][0]), "r"(af[mt][1]), "r"(af[mt][2]), "r"(af[mt][3]),
                          "r"(bf[nt][0]), "r"(bf[nt][1]));
                }
        }
        __syncthreads();
    }

    // epilogue: write C tiles
    #pragma unroll
    for (int mt = 0; mt < 4; mt++) {
        int row = m0 + warp_m*64 + mt*16 + g;
        #pragma unroll
        for (int nt = 0; nt < 4; nt++) {
            int col = n0 + warp_n*32 + nt*8 + 2*tg;
            *(float2*)&g_xm[(size_t)row*INNER_ + col]     = make_float2(c[mt][nt][0], c[mt][nt][1]);
            *(float2*)&g_xm[(size_t)(row+8)*INNER_ + col] = make_float2(c[mt][nt][2], c[mt][nt][3]);
        }
    }
}

// ---------------- K3: causal conv + silu + block-diag q/k/v ----------------
__global__ void k3_conv_qkv(const float* __restrict__ convw, const float* __restrict__ convb,
                            const float* __restrict__ qw, const float* __restrict__ kw,
                            const float* __restrict__ vw)
{
    int n  = threadIdx.x;
    int b  = blockIdx.y;
    int s0 = blockIdx.x * 8;

    float cw[4][4], cb[4], qwr[4][4], kwr[4][4], vwr[4][4];
    #pragma unroll
    for (int o = 0; o < 4; o++) {
        cb[o] = convb[4*n + o];
        #pragma unroll
        for (int j = 0; j < 4; j++) cw[o][j] = convw[(4*n+o)*4 + j];
        #pragma unroll
        for (int i = 0; i < 4; i++) {
            qwr[o][i] = qw[(n*4+o)*4 + i];
            kwr[o][i] = kw[(n*4+o)*4 + i];
            vwr[o][i] = vw[(n*4+o)*4 + i];
        }
    }

    float win[4][4];                 // win[j] = x_m at s-3+j
    #pragma unroll
    for (int j = 0; j < 3; j++) {
        int s = s0 - 3 + j;
        if (s >= 0) {
            float4 t = *(const float4*)&g_xm[((size_t)b*S_ + s)*INNER_ + 4*n];
            win[j][0]=t.x; win[j][1]=t.y; win[j][2]=t.z; win[j][3]=t.w;
        } else {
            win[j][0]=win[j][1]=win[j][2]=win[j][3]=0.f;
        }
    }
    int h = n >> 6;
    int dbase = (n & 63) * 4;

    for (int ss = 0; ss < 8; ss++) {
        int s = s0 + ss;
        {
            float4 t = *(const float4*)&g_xm[((size_t)b*S_ + s)*INNER_ + 4*n];
            win[3][0]=t.x; win[3][1]=t.y; win[3][2]=t.z; win[3][3]=t.w;
        }
        float xa[4];
        #pragma unroll
        for (int o = 0; o < 4; o++) {
            float acc = cb[o];
            #pragma unroll
            for (int j = 0; j < 4; j++) acc += win[j][o] * cw[o][j];
            xa[o] = silu_f(acc);
        }
        float qv[4], kv4[4], vv[4];
        #pragma unroll
        for (int o = 0; o < 4; o++) {
            float a = 0.f, bk = 0.f, c2 = 0.f;
            #pragma unroll
            for (int i = 0; i < 4; i++) {
                a  += xa[i]     * qwr[o][i];
                bk += xa[i]     * kwr[o][i];
                c2 += win[3][i] * vwr[o][i];
            }
            qv[o] = a; kv4[o] = bk; vv[o] = c2;
        }
        size_t base = (((size_t)b*NH_ + h)*S_ + s)*DH_ + dbase;
        *(float4*)&g_q[base] = make_float4(qv[0],qv[1],qv[2],qv[3]);
        *(float4*)&g_k[base] = make_float4(kv4[0],kv4[1],kv4[2],kv4[3]);
        *(float4*)&g_v[base] = make_float4(vv[0],vv[1],vv[2],vv[3]);
        if (s == S_-1)
            *(float4*)&g_xa_last[b*INNER_ + 4*n] = make_float4(xa[0],xa[1],xa[2],xa[3]);

        #pragma unroll
        for (int o = 0; o < 4; o++) { win[0][o]=win[1][o]; win[1][o]=win[2][o]; win[2][o]=win[3][o]; }
    }
}

// ---------------- K3b: ig/fg gates, float4-vectorized ----------------
// warp: 4 t-rows; lanes cover 128 channels per iter via float4 (8 iters over 1024)
__global__ void k3b_gates(const float* __restrict__ igw, const float* __restrict__ igb,
                          const float* __restrict__ fgw, const float* __restrict__ fgb)
{
    int tid = threadIdx.x;
    int lane = tid & 31, w = tid >> 5;   // 8 warps
    int blk = blockIdx.x;                // 512 blocks
    int b = blk >> 4;
    int t0 = (blk & 15) * 32 + w * 4;

    float aI[4][4], aF[4][4];
    #pragma unroll
    for (int r = 0; r < 4; r++)
        #pragma unroll
        for (int g = 0; g < 4; g++) { aI[r][g] = 0.f; aF[r][g] = 0.f; }

    const float* segp[3] = { g_q, g_k, g_v };
    #pragma unroll
    for (int seg = 0; seg < 3; seg++) {
        const float* P = segp[seg];
        #pragma unroll
        for (int c0 = 0; c0 < INNER_; c0 += 128) {
            int hh = c0 >> 8;
            int dd = (c0 & 255) + lane*4;
            int cw = c0 + lane*4;
            float4 wI4[4], wF4[4];
            #pragma unroll
            for (int g = 0; g < 4; g++) {
                wI4[g] = *(const float4*)&igw[g*3072 + seg*1024 + cw];
                wF4[g] = *(const float4*)&fgw[g*3072 + seg*1024 + cw];
            }
            size_t rb = (((size_t)b*NH_ + hh)*S_ + t0)*DH_ + dd;
            #pragma unroll
            for (int r = 0; r < 4; r++) {
                float4 val = *(const float4*)&P[rb + (size_t)r*DH_];
                #pragma unroll
                for (int g = 0; g < 4; g++) {
                    aI[r][g] += val.x*wI4[g].x + val.y*wI4[g].y + val.z*wI4[g].z + val.w*wI4[g].w;
                    aF[r][g] += val.x*wF4[g].x + val.y*wF4[g].y + val.z*wF4[g].z + val.w*wF4[g].w;
                }
            }
        }
    }
    #pragma unroll
    for (int r = 0; r < 4; r++) {
        #pragma unroll
        for (int g = 0; g < 4; g++) {
            float sI = aI[r][g], sF = aF[r][g];
            #pragma unroll
            for (int o = 16; o > 0; o >>= 1) {
                sI += __shfl_xor_sync(0xffffffffu, sI, o);
                sF += __shfl_xor_sync(0xffffffffu, sF, o);
            }
            if (lane == 0) {
                int t = t0 + r;
                g_ig[(b*NH_+g)*S_ + t] = sI + igb[g];
                float fgv = sF + fgb[g];
                float lf = (fgv >= 0.f) ? -log1pf(expf(-fgv)) : (fgv - log1pf(expf(fgv)));
                g_lf[(b*NH_+g)*S_ + t] = lf;
            }
        }
    }
}

// ---------------- K4: mLSTM last-row + head-LN + hs ----------------
__global__ void k4_mlstm(const float* __restrict__ wup, const float* __restrict__ onormw,
                         const float* __restrict__ skipw)
{
    int tid = threadIdx.x;               // 256
    int lane = tid & 31, wrp = tid >> 5; // 8 warps
    int b = blockIdx.x >> 2, h = blockIdx.x & 3;
    size_t bh = (size_t)b*NH_ + h;

    __shared__ float s_q[DH_];
    __shared__ float s_w[S_];
    __shared__ float s_qk[S_];
    __shared__ float s_hr[E_];
    __shared__ float s_z[DH_];
    __shared__ float red[256];
    __shared__ float wtot[8], woff[8];

    s_q[tid] = g_q[(bh*S_ + (S_-1))*DH_ + tid];
    s_hr[tid]       = g_h[((size_t)b*S_ + (S_-1))*E_ + tid];
    s_hr[tid + 256] = g_h[((size_t)b*S_ + (S_-1))*E_ + tid + 256];

    int t0 = 2*tid, t1 = 2*tid + 1;
    float lf0 = g_lf[bh*S_ + t0], lf1 = g_lf[bh*S_ + t1];
    float ig0 = g_ig[bh*S_ + t0], ig1 = g_ig[bh*S_ + t1];

    // block inclusive scan of lf (2 elems/thread)
    float v = lf0 + lf1;
    #pragma unroll
    for (int o = 1; o < 32; o <<= 1) {
        float u = __shfl_up_sync(0xffffffffu, v, o);
        if (lane >= o) v += u;
    }
    if (lane == 31) wtot[wrp] = v;
    __syncthreads();
    if (tid < 8) { float t = 0.f; for (int i = 0; i < tid; i++) t += wtot[i]; woff[tid] = t; }
    __syncthreads();
    float cin  = v + woff[wrp];          // inclusive prefix through t1
    float c0   = cin - lf1;              // inclusive prefix through t0
    float total = woff[7] + wtot[7];
    float logd0 = (total - c0)  + ig0;
    float logd1 = (total - cin) + ig1;

    // block max
    red[tid] = fmaxf(logd0, logd1);
    __syncthreads();
    for (int o = 128; o > 0; o >>= 1) { if (tid < o) red[tid] = fmaxf(red[tid], red[tid+o]); __syncthreads(); }
    float maxd = red[0];
    __syncthreads();

    float d0 = expf(logd0 - maxd), d1 = expf(logd1 - maxd);
    s_w[t0] = d0; s_w[t1] = d1;
    __syncthreads();

    // qk[t] = (q_last . k_t) / 16  — warp per t
    const float* kb = g_k + bh*S_*DH_;
    for (int t = wrp; t < S_; t += 8) {
        const float* kr = kb + (size_t)t*DH_;
        float p = 0.f;
        #pragma unroll
        for (int d = lane; d < DH_; d += 32) p += s_q[d]*kr[d];
        #pragma unroll
        for (int o = 16; o > 0; o >>= 1) p += __shfl_xor_sync(0xffffffffu, p, o);
        if (lane == 0) s_qk[t] = p * 0.0625f;
    }
    __syncthreads();

    float cm0 = s_qk[t0]*d0, cm1 = s_qk[t1]*d1;
    red[tid] = cm0 + cm1;
    __syncthreads();
    for (int o = 128; o > 0; o >>= 1) { if (tid < o) red[tid] += red[tid+o]; __syncthreads(); }
    float csum = red[0];
    __syncthreads();
    float inv = 1.f / (fmaxf(fabsf(csum), expf(-maxd)) + 1e-6f);
    s_w[t0] = cm0*inv; s_w[t1] = cm1*inv;
    __syncthreads();

    // z_last via warp-cooperative coalesced dot products
    for (int j = 0; j < 32; j++) {
        int cl = wrp*32 + j;
        const float* wz = wup + (size_t)(INNER_ + h*DH_ + cl)*E_;
        float p = 0.f;
        #pragma unroll
        for (int i = 0; i < 4; i++) {
            float4 t = *(const float4*)&wz[lane*4 + i*128];
            int e = lane*4 + i*128;
            p += s_hr[e]*t.x + s_hr[e+1]*t.y + s_hr[e+2]*t.z + s_hr[e+3]*t.w;
        }
        #pragma unroll
        for (int o = 16; o > 0; o >>= 1) p += __shfl_xor_sync(0xffffffffu, p, o);
        if (lane == 0) s_z[cl] = p;
    }

    // hc[d] = sum_t w[t]*v[t][d]
    const float* vb = g_v + bh*S_*DH_;
    float acc = 0.f;
    #pragma unroll 4
    for (int t = 0; t < S_; t++) acc += s_w[t]*vb[(size_t)t*DH_ + tid];

    // LN over DH (no weight)
    red[tid] = acc; __syncthreads();
    for (int o = 128; o > 0; o >>= 1) { if (tid < o) red[tid] += red[tid+o]; __syncthreads(); }
    float mu = red[0] * (1.f/DH_);
    __syncthreads();
    red[tid] = acc*acc; __syncthreads();
    for (int o = 128; o > 0; o >>= 1) { if (tid < o) red[tid] += red[tid+o]; __syncthreads(); }
    float var = red[0]*(1.f/DH_) - mu*mu;
    float hn = (acc - mu) * rsqrtf(var + 1e-5f);

    int c = h*DH_ + tid;
    float z = s_z[tid];
    float hs = (hn*onormw[c] + skipw[c]*g_xa_last[b*INNER_ + c]) * silu_f(z);
    g_hs[b*INNER_ + c] = hs;
}

// ---------------- K5: down-proj (last pos) + post-LN + head ----------------
__global__ void k5_final(const float* __restrict__ wdown, const float* __restrict__ lnpw,
                         const float* __restrict__ fcw, const float* __restrict__ fcb,
                         float* __restrict__ out)
{
    int b = blockIdx.x;
    int tid = threadIdx.x;               // 512 threads, 16 warps
    int lane = tid & 31, wrp = tid >> 5;

    __shared__ float s_hs[INNER_];
    __shared__ float s_y[E_];
    __shared__ float red[512];

    s_hs[tid]       = g_hs[b*INNER_ + tid];
    s_hs[tid + 512] = g_hs[b*INNER_ + tid + 512];
    __syncthreads();

    for (int e = wrp; e < E_; e += 16) {
        const float* wr = wdown + (size_t)e*INNER_;
        float p = 0.f;
        #pragma unroll
        for (int c = lane; c < INNER_; c += 32) p += s_hs[c]*wr[c];
        #pragma unroll
        for (int o = 16; o > 0; o >>= 1) p += __shfl_xor_sync(0xffffffffu, p, o);
        if (lane == 0) s_y[e] = g_res_last[b*E_ + e] + p;
    }
    __syncthreads();

    float xv = s_y[tid];
    red[tid] = xv; __syncthreads();
    for (int o = 256; o > 0; o >>= 1) { if (tid < o) red[tid] += red[tid+o]; __syncthreads(); }
    float mean = red[0] * (1.f/E_);
    __syncthreads();
    red[tid] = xv*xv; __syncthreads();
    for (int o = 256; o > 0; o >>= 1) { if (tid < o) red[tid] += red[tid+o]; __syncthreads(); }
    float var = red[0]*(1.f/E_) - mean*mean;
    float xf = (xv - mean) * rsqrtf(var + 1e-5f) * lnpw[tid];
    __syncthreads();
    red[tid] = xf * fcw[tid]; __syncthreads();
    for (int o = 256; o > 0; o >>= 1) { if (tid < o) red[tid] += red[tid+o]; __syncthreads(); }
    if (tid == 0) out[b] = 1.f / (1.f + expf(-(red[0] + fcb[0])));
}

// ---------------- launch ----------------
extern "C" void kernel_launch(void* const* d_in, const int* in_sizes, int n_in,
                              void* d_out, int out_size)
{
    const int*   tokens = (const int*)  d_in[0];
    const float* emb    = (const float*)d_in[1];
    const float* ln1w   = (const float*)d_in[2];
    const float* convw  = (const float*)d_in[3];
    const float* convb  = (const float*)d_in[4];
    const float* wup    = (const float*)d_in[5];
    const float* qw     = (const float*)d_in[6];
    const float* kw     = (const float*)d_in[7];
    const float* vw     = (const float*)d_in[8];
    const float* igw    = (const float*)d_in[9];
    const float* igb    = (const float*)d_in[10];
    const float* fgw    = (const float*)d_in[11];
    const float* fgb    = (const float*)d_in[12];
    const float* onormw = (const float*)d_in[13];
    const float* skipw  = (const float*)d_in[14];
    const float* wdown  = (const float*)d_in[15];
    const float* lnpw   = (const float*)d_in[16];
    const float* fcw    = (const float*)d_in[17];
    const float* fcb    = (const float*)d_in[18];
    float* out = (float*)d_out;

    cudaFuncSetAttribute(k2_gemm_up, cudaFuncAttributeMaxDynamicSharedMemorySize, K2_SMEM);

    k0_round_wup<<<(INNER_*E_)/(256*4), 256>>>(wup);
    k1_embed_ln<<<M_TOK, 256>>>(tokens, emb, ln1w);
    dim3 g2(INNER_/TBN, M_TOK/TBM);
    k2_gemm_up<<<g2, 256, K2_SMEM>>>();
    dim3 g3(S_/8, B_);
    k3_conv_qkv<<<g3, 256>>>(convw, convb, qw, kw, vw);
    k3b_gates<<<512, 256>>>(igw, igb, fgw, fgb);
    k4_mlstm<<<B_*NH_, 256>>>(wup, onormw, skipw);
    k5_final<<<B_, 512>>>(wdown, lnpw, fcw, fcb, out);
}